// round 16
// baseline (speedup 1.0000x reference)
#include <cuda_runtime.h>
#include <cstdint>

// ---------------- problem constants ----------------
#define HDIM 256
#define WDIM 256
#define FCH  1024
#define KTOP 2000
#define MAXOUT 500
#define CROPSZ 48
#define NPIX (HDIM*WDIM)           // 65536

// output layout (float32, concatenated in reference tuple order)
#define OFF_SCORES 0
#define OFF_DEC    500
#define OFF_IOUT   1500
#define OFF_ICRD   (1500 + 500*48*48)

// ---------------- device scratch ----------------
__device__ float g_y1[(size_t)NPIX * FCH];        // 268 MB
__device__ float g_part[(size_t)NPIX * 8 * 3];    // per-(row, bn) proj partials
__device__ float g_reg[NPIX * 2];
__device__ unsigned long long g_keys[NPIX];
__device__ int   g_hist1[4096];
__device__ int   g_hist2[4096];
__device__ int   g_cnt[4];        // [0]=compact count [1]=b* [2]=k2 [3]=s*
__device__ unsigned long long g_buf[4096];
__device__ float g_gy[KTOP], g_gx[KTOP], g_ts[KTOP];
__device__ unsigned g_close[KTOP * 64];
__device__ int   g_start[MAXOUT * 2];
__device__ __align__(16) float g_h[(size_t)MAXOUT * CROPSZ * CROPSZ * 64];

// ---------------- f32x2 helpers (sm_103a packed fp32, IEEE per lane) ------
__device__ __forceinline__ unsigned long long ffma2(unsigned long long a,
                                                    unsigned long long b,
                                                    unsigned long long c) {
    unsigned long long d;
    asm("fma.rn.f32x2 %0, %1, %2, %3;" : "=l"(d) : "l"(a), "l"(b), "l"(c));
    return d;
}
__device__ __forceinline__ unsigned long long pack2(float v) {
    unsigned long long d;
    asm("mov.b64 %0, {%1, %1};" : "=l"(d) : "f"(v));
    return d;
}

// ================= zero scratch (graph-replay safe) =====================
__global__ void zero_kernel()
{
    int i = blockIdx.x * blockDim.x + threadIdx.x;
    if (i < 4096) { g_hist1[i] = 0; g_hist2[i] = 0; g_buf[i] = 0ull; }
    if (i < 4) g_cnt[i] = 0;
}

// ================= GEMM: C = relu(A*B + bias), double-buffered ==========
// R7-proven config: KT=16, 34.8 KB static smem, grid(512,8) bm-fastest.
// Profiled: fma=74.2%, L1=74.0% co-saturated — structural ceiling.
// MODE 0: implicit 3x3 conv (A=[256,256,128] HWC, B=Wc[1152,1024]) -> g_y1
// MODE 1: A=g_y1 [65536,1024], B=Wfc -> fused proj partials (no C store)
template<int MODE>
__global__ __launch_bounds__(256, 2)
void gemm_kernel(const float* __restrict__ Aext,
                 const float* __restrict__ B,
                 const float* __restrict__ bias,
                 const float* __restrict__ Ws,
                 const float* __restrict__ Wr)
{
    __shared__ __align__(16) float As[2][16 * 136];
    __shared__ __align__(16) float Bs[2][16 * 136];

    const int Ktot = MODE ? 1024 : 1152;
    const int NT = Ktot / 16;
    const float* A = MODE ? g_y1 : Aext;

    int tid = threadIdx.x;
    int tx = tid & 15, ty = tid >> 4;
    int bm = blockIdx.x, bn = blockIdx.y;
    int row0 = bm * 128;
    int co0  = bn * 128;
    int yrow = bm >> 1;                // conv mode
    int x0   = (bm & 1) * 128;

    int aci  = tid & 15;               // K index within tile
    int apx0 = tid >> 4;               // px start
    int bco  = tid & 127;
    int bk0  = tid >> 7;

    unsigned long long acc[8][4];
#pragma unroll
    for (int i = 0; i < 8; i++)
#pragma unroll
        for (int j = 0; j < 4; j++) acc[i][j] = 0ull;

    float Ar[8], Br[8];

    auto load_regs = [&](int k0) {
        if (MODE == 0) {
            int tap = k0 >> 7;
            int ci  = (k0 & 127) + aci;
            int dy  = tap / 3 - 1;
            int dxo = tap % 3 - 1;
            int syy = yrow + dy;
            bool rv = ((unsigned)syy < 256u);
#pragma unroll
            for (int i = 0; i < 8; i++) {
                int sxx = x0 + apx0 + i * 16 + dxo;
                float v = 0.f;
                if (rv && ((unsigned)sxx < 256u))
                    v = Aext[((size_t)(syy * 256 + sxx)) * 128 + ci];
                Ar[i] = v;
            }
        } else {
#pragma unroll
            for (int i = 0; i < 8; i++)
                Ar[i] = A[(size_t)(row0 + apx0 + i * 16) * 1024 + k0 + aci];
        }
#pragma unroll
        for (int i = 0; i < 8; i++)
            Br[i] = B[(size_t)(k0 + bk0 + i * 2) * 1024 + co0 + bco];
    };
    auto store_tile = [&](int buf) {
#pragma unroll
        for (int i = 0; i < 8; i++)
            As[buf][aci * 136 + apx0 + i * 16] = Ar[i];
#pragma unroll
        for (int i = 0; i < 8; i++)
            Bs[buf][(bk0 + i * 2) * 136 + bco] = Br[i];
    };

    load_regs(0);
    store_tile(0);
    __syncthreads();

    for (int kt = 0; kt < NT; kt++) {
        int cur = kt & 1;
        if (kt + 1 < NT) load_regs((kt + 1) * 16);

#pragma unroll
        for (int k = 0; k < 16; k++) {
            float4 a0 = *(const float4*)&As[cur][k * 136 + ty * 8];
            float4 a1 = *(const float4*)&As[cur][k * 136 + ty * 8 + 4];
            unsigned long long b0 = *(const unsigned long long*)&Bs[cur][k * 136 + tx * 2];
            unsigned long long b1 = *(const unsigned long long*)&Bs[cur][k * 136 + tx * 2 + 32];
            unsigned long long b2 = *(const unsigned long long*)&Bs[cur][k * 136 + tx * 2 + 64];
            unsigned long long b3 = *(const unsigned long long*)&Bs[cur][k * 136 + tx * 2 + 96];
            float av[8] = {a0.x, a0.y, a0.z, a0.w, a1.x, a1.y, a1.z, a1.w};
#pragma unroll
            for (int i = 0; i < 8; i++) {
                unsigned long long aa = pack2(av[i]);
                acc[i][0] = ffma2(aa, b0, acc[i][0]);
                acc[i][1] = ffma2(aa, b1, acc[i][1]);
                acc[i][2] = ffma2(aa, b2, acc[i][2]);
                acc[i][3] = ffma2(aa, b3, acc[i][3]);
            }
        }
        if (kt + 1 < NT) store_tile(cur ^ 1);
        __syncthreads();
    }

    if (MODE == 0) {
#pragma unroll
        for (int i = 0; i < 8; i++) {
            int row = row0 + ty * 8 + i;
#pragma unroll
            for (int j = 0; j < 4; j++) {
                float2 v = *reinterpret_cast<float2*>(&acc[i][j]);
                int co = co0 + tx * 2 + j * 32;
                float o0 = v.x + bias[co];
                float o1 = v.y + bias[co + 1];
                o0 = o0 > 0.f ? o0 : 0.f;
                o1 = o1 > 0.f ? o1 : 0.f;
                *(float2*)&g_y1[(size_t)row * 1024 + co] = make_float2(o0, o1);
            }
        }
    } else {
        float wsv[8], wr0[8], wr1[8], bv[8];
#pragma unroll
        for (int j = 0; j < 4; j++) {
            int co = co0 + tx * 2 + j * 32;
            wsv[2*j]   = Ws[co];      wsv[2*j+1] = Ws[co+1];
            wr0[2*j]   = Wr[2*co];    wr0[2*j+1] = Wr[2*co+2];
            wr1[2*j]   = Wr[2*co+1];  wr1[2*j+1] = Wr[2*co+3];
            bv[2*j]    = bias[co];    bv[2*j+1]  = bias[co+1];
        }
#pragma unroll
        for (int i = 0; i < 8; i++) {
            int row = row0 + ty * 8 + i;
            float s = 0.f, r0 = 0.f, r1 = 0.f;
#pragma unroll
            for (int j = 0; j < 4; j++) {
                float2 v = *reinterpret_cast<float2*>(&acc[i][j]);
                float o0 = v.x + bv[2*j];   o0 = o0 > 0.f ? o0 : 0.f;
                float o1 = v.y + bv[2*j+1]; o1 = o1 > 0.f ? o1 : 0.f;
                s  = fmaf(o0, wsv[2*j], s);   s  = fmaf(o1, wsv[2*j+1], s);
                r0 = fmaf(o0, wr0[2*j], r0);  r0 = fmaf(o1, wr0[2*j+1], r0);
                r1 = fmaf(o0, wr1[2*j], r1);  r1 = fmaf(o1, wr1[2*j+1], r1);
            }
#pragma unroll
            for (int off = 8; off; off >>= 1) {
                s  += __shfl_down_sync(0xffffffffu, s,  off, 16);
                r0 += __shfl_down_sync(0xffffffffu, r0, off, 16);
                r1 += __shfl_down_sync(0xffffffffu, r1, off, 16);
            }
            if (tx == 0) {
                size_t o = ((size_t)row * 8 + bn) * 3;
                g_part[o] = s; g_part[o+1] = r0; g_part[o+2] = r1;
            }
        }
    }
}

// ================= proj reduce: scores/reg/keys/hist ====================
__global__ void proj_reduce_kernel(const float* __restrict__ bs,
                                   const float* __restrict__ br)
{
    int row = blockIdx.x * blockDim.x + threadIdx.x;
    if (row >= NPIX) return;
    float s = 0.f, r0 = 0.f, r1 = 0.f;
    const float* p = &g_part[(size_t)row * 24];
#pragma unroll
    for (int bn = 0; bn < 8; bn++) {
        s  += p[bn*3];
        r0 += p[bn*3+1];
        r1 += p[bn*3+2];
    }
    float z = s + bs[0];
    float score = 1.f / (1.f + expf(-z));
    g_reg[2*row]   = r0 + br[0];
    g_reg[2*row+1] = r1 + br[1];
    unsigned sb = __float_as_uint(score);
    g_keys[row] = ((unsigned long long)sb << 32) | (unsigned)(~row);
    atomicAdd(&g_hist1[sb >> 20], 1);
}

// ================= histogram scan (suffix sums, find threshold) =========
// (histogram selected INSIDE the kernel — host-decayed __device__ pointers
//  silently read host shadow memory via ATS on GB300.)
__global__ void scan_kernel(int mode)
{
    __shared__ int sA[4096], sB[4096];
    const int* hist = (mode == 0) ? g_hist1 : g_hist2;
    int t = threadIdx.x;
    for (int i = t; i < 4096; i += 1024) sA[i] = hist[i];
    __syncthreads();
    int* src = sA; int* dst = sB;
    for (int d = 1; d < 4096; d <<= 1) {
        for (int i = t; i < 4096; i += 1024)
            dst[i] = src[i] + ((i + d < 4096) ? src[i + d] : 0);
        __syncthreads();
        int* tmp = src; src = dst; dst = tmp;
    }
    int kneed = (mode == 0) ? KTOP : g_cnt[2];
    for (int i = t; i < 4096; i += 1024) {
        if (src[i] >= kneed && (i == 4095 || src[i + 1] < kneed)) {
            if (mode == 0) {
                g_cnt[1] = i;
                g_cnt[2] = kneed - ((i < 4095) ? src[i + 1] : 0);
            } else {
                g_cnt[3] = i;
            }
        }
    }
}

__global__ void hist2_build_kernel()
{
    int i = blockIdx.x * blockDim.x + threadIdx.x;
    if (i >= NPIX) return;
    unsigned sb = (unsigned)(g_keys[i] >> 32);
    if ((int)(sb >> 20) == g_cnt[1])
        atomicAdd(&g_hist2[(sb >> 8) & 4095], 1);
}

__global__ void compact_kernel()
{
    int i = blockIdx.x * blockDim.x + threadIdx.x;
    if (i >= NPIX) return;
    unsigned long long key = g_keys[i];
    unsigned sb = (unsigned)(key >> 32);
    int bin = sb >> 20;
    int bstar = g_cnt[1], sstar = g_cnt[3];
    bool take = (bin > bstar) ||
                (bin == bstar && (int)((sb >> 8) & 4095) >= sstar);
    if (take) {
        int pos = atomicAdd(&g_cnt[0], 1);
        if (pos < 4096) g_buf[pos] = key;
    }
}

// sort 4096 keys (asc) in one block, gather top-2000 desc
__global__ void sortgather_kernel()
{
    __shared__ unsigned long long s[4096];
    int t = threadIdx.x;
    s[t] = g_buf[t]; s[t + 1024] = g_buf[t + 1024];
    s[t + 2048] = g_buf[t + 2048]; s[t + 3072] = g_buf[t + 3072];
    __syncthreads();
    for (int k = 2; k <= 4096; k <<= 1) {
        for (int j = k >> 1; j > 0; j >>= 1) {
#pragma unroll
            for (int p = 0; p < 2; p++) {
                int t2 = t + p * 1024;
                int i = ((t2 & ~(j - 1)) << 1) | (t2 & (j - 1));
                bool up = ((i & k) == 0);
                unsigned long long a = s[i], b = s[i + j];
                if ((a > b) == up) { s[i] = b; s[i + j] = a; }
            }
            __syncthreads();
        }
    }
    for (int r = t; r < KTOP; r += 1024) {
        unsigned long long e = s[4095 - r];
        unsigned idx = ~(unsigned)(e & 0xffffffffu);
        float sc = __uint_as_float((unsigned)(e >> 32));
        int yy = idx >> 8, xx = idx & 255;
        g_ts[r] = sc;
        g_gy[r] = (float)yy + 0.5f + g_reg[2 * idx];
        g_gx[r] = (float)xx + 0.5f + g_reg[2 * idx + 1];
    }
}

// ================= NMS ==================================================
__global__ void nms_build_kernel()
{
    int i = blockIdx.x;
    int w = threadIdx.x;
    float cy = g_gy[i], cx = g_gx[i];
    unsigned m = 0;
    if (w < 63) {
        int j0 = w * 32;
#pragma unroll 4
        for (int l = 0; l < 32; l++) {
            int j = j0 + l;
            if (j > i && j < KTOP) {
                float dy = g_gy[j] - cy, dx = g_gx[j] - cx;
                if (dy * dy + dx * dx < 1.0f) m |= 1u << l;
            }
        }
    }
    g_close[i * 64 + w] = m;
}

__global__ void nms_serial_kernel(float* __restrict__ out)
{
    __shared__ float sy[KTOP], sx[KTOP], ss[KTOP];
    __shared__ unsigned supw[64];
    __shared__ int sel[MAXOUT];
    int t = threadIdx.x;
    for (int i = t; i < KTOP; i += 1024) {
        sy[i] = g_gy[i]; sx[i] = g_gx[i]; ss[i] = g_ts[i];
    }
    if (t < 32) {   // warp 0: serial bitmask OR loop
        int lane = t;
        unsigned s0 = 0, s1 = 0;
        unsigned p0 = g_close[lane], p1 = g_close[lane + 32];
        for (int i = 0; i < KTOP; i++) {
            unsigned n0 = 0, n1 = 0;
            if (i + 1 < KTOP) {
                n0 = g_close[(i + 1) * 64 + lane];
                n1 = g_close[(i + 1) * 64 + lane + 32];
            }
            int wi = i >> 5;
            unsigned myv = (wi >= 32) ? s1 : s0;
            unsigned vv = __shfl_sync(0xffffffffu, myv, wi & 31);
            if (!((vv >> (i & 31)) & 1u)) { s0 |= p0; s1 |= p1; }
            p0 = n0; p1 = n1;
        }
        supw[lane] = s0; supw[lane + 32] = s1;
    }
    __syncthreads();
    if (t == 0) {
        int cnt = 0;
        for (int i = 0; i < KTOP && cnt < MAXOUT; i++)
            if (!((supw[i >> 5] >> (i & 31)) & 1u)) sel[cnt++] = i;
        for (int i = 0; i < KTOP && cnt < MAXOUT; i++)
            if ((supw[i >> 5] >> (i & 31)) & 1u) sel[cnt++] = i;
    }
    __syncthreads();
    if (t < MAXOUT) {
        int i = sel[t];
        bool sup = (supw[i >> 5] >> (i & 31)) & 1u;
        out[OFF_SCORES + t] = sup ? -1.0f : ss[i];
        out[OFF_DEC + 2 * t]     = sy[i] * 4.0f;
        out[OFF_DEC + 2 * t + 1] = sx[i] * 4.0f;
        float ly = sy[i] * 2.0f, lx = sx[i] * 2.0f;
        int sty = (int)fminf(fmaxf(rintf(ly - 24.0f), 0.f), 464.f);
        int stx = (int)fminf(fmaxf(rintf(lx - 24.0f), 0.f), 464.f);
        g_start[2 * t]     = sty;
        g_start[2 * t + 1] = stx;
    }
}

// ================= instance head ========================================
// conv1 (R13): half-crop blocks, grid (500,2) — wave-quantization fix.
#define IC_WFLOATS 18432                    // 9*32*64
#define IC_SLABROW (32 * 52)                // floats per slab row
#define IC_SLABFLOATS (10 * IC_SLABROW)     // 16640
#define IC_SMEM ((IC_WFLOATS + IC_SLABFLOATS) * 4)   // 140,288 B
__global__ __launch_bounds__(256, 1)
void icv1_kernel(const float* __restrict__ seg,
                 const float* __restrict__ Wi, const float* __restrict__ bi)
{
    extern __shared__ __align__(16) float dyn[];
    float* w_sh = dyn;                    // [tap*2048 + ci*64 + ch]
    float* slab = dyn + IC_WFLOATS;       // [(d*32 + ci)*52 + xx]

    int crop = blockIdx.x;
    int half = blockIdx.y;                // 0: rows 0..23, 1: rows 24..47
    int t = threadIdx.x;
    int lane = t & 31, wrp = t >> 5;      // 8 warps -> 8 rows per chunk
    int sy0 = g_start[2 * crop], sx0 = g_start[2 * crop + 1];

    for (int i = t; i < IC_WFLOATS; i += 256) w_sh[i] = Wi[i];
    float2 bp = *(const float2*)&bi[2 * lane];

    for (int c = 0; c < 3; c++) {
        int chunk = half * 3 + c;
        int gr0 = chunk * 8 - 1;
        __syncthreads();                  // prev chunk readers done
        for (int idx = t; idx < IC_SLABFLOATS; idx += 256) {
            int d = idx / IC_SLABROW;
            int rem = idx - d * IC_SLABROW;
            int xx = rem >> 5, ci = rem & 31;
            int gr = gr0 + d, xc = xx - 1;
            float v = 0.f;
            if ((unsigned)gr < 48u && (unsigned)xc < 48u)
                v = seg[((size_t)(sy0 + gr) * 512 + (sx0 + xc)) * 32 + ci];
            slab[(d * 32 + ci) * 52 + xx] = v;
        }
        __syncthreads();

        int r = chunk * 8 + wrp;
        unsigned long long acc2[48];
#pragma unroll
        for (int p = 0; p < 48; p++) acc2[p] = 0ull;

        for (int dy = 0; dy < 3; dy++) {
            const float* srow = &slab[(wrp + dy) * 32 * 52];
            const float* wbase = &w_sh[dy * 3 * 2048 + 2 * lane];
            for (int ci = 0; ci < 32; ci++) {
                const float* sr = srow + ci * 52;
                unsigned long long w0 = *(const unsigned long long*)&wbase[ci * 64];
                unsigned long long w1 = *(const unsigned long long*)&wbase[2048 + ci * 64];
                unsigned long long w2 = *(const unsigned long long*)&wbase[4096 + ci * 64];
#pragma unroll
                for (int j = 0; j < 13; j++) {
                    float4 a4 = *(const float4*)&sr[4 * j];
                    float av[4] = {a4.x, a4.y, a4.z, a4.w};
#pragma unroll
                    for (int l = 0; l < 4; l++) {
                        const int xx = 4 * j + l;
                        if (xx > 49) continue;
                        unsigned long long aa = pack2(av[l]);
                        if (xx <= 47)            acc2[xx]     = ffma2(aa, w0, acc2[xx]);
                        if (xx >= 1 && xx <= 48) acc2[xx - 1] = ffma2(aa, w1, acc2[xx - 1]);
                        if (xx >= 2)             acc2[xx - 2] = ffma2(aa, w2, acc2[xx - 2]);
                    }
                }
            }
        }

        float* dst = &g_h[(((size_t)crop * 48 + r) * 48) * 64 + 2 * lane];
#pragma unroll
        for (int px = 0; px < 48; px++) {
            float2 v = *reinterpret_cast<float2*>(&acc2[px]);
            float o0 = v.x + bp.x, o1 = v.y + bp.y;
            o0 = o0 > 0.f ? o0 : 0.f;
            o1 = o1 > 0.f ? o1 : 0.f;
            *(float2*)&dst[px * 64] = make_float2(o0, o1);
        }
    }
}

// conv2 (R16): R14 structure + ONE change — 4-slab rolling window with
// quad-shuffle reduction -> single __syncthreads per row (48 -> 24/block).
// Slab being loaded ((r+2)&3) never aliases slabs being read (r-1,r,r+1),
// so threads >=192 overlap the load with compute. Layout and inner loop
// identical to R14 (scalar fmaf, xx*64+co). Output-2 reduction order
// changes (quad shuffle vs red[] sum) — ~1e-7 shift, tolerance 1e-3.
#define IC2_SLABF 3200                    // 50 * 64
#define IC2_SMEM  (4 * IC2_SLABF * 4)     // 51,200 B dynamic
__global__ __launch_bounds__(256)
void icv2_kernel(const float* __restrict__ Wo, const float* __restrict__ bo,
                 float* __restrict__ out)
{
    extern __shared__ __align__(16) float h4[];   // 4 slabs
    __shared__ __align__(16) float w2[576];
    int crop = blockIdx.x;
    int half = blockIdx.y;
    int r0 = half * 24;
    int t = threadIdx.x;
    int sy0 = g_start[2 * crop], sx0 = g_start[2 * crop + 1];
    for (int w = t; w < 576; w += 256) w2[w] = Wo[w];

    // coords for this half-crop (rows r0..r0+23)
    for (int idx = t; idx < 24 * CROPSZ; idx += 256) {
        int cy = r0 + idx / 48, cx = idx % 48;
        size_t o = OFF_ICRD + 2 * ((size_t)crop * 2304 + (size_t)cy * 48 + cx);
        out[o]     = (float)(sy0 + cy);
        out[o + 1] = (float)(sx0 + cx);
    }

    auto load_slab = [&](int rr) {
        float* dst = &h4[(rr & 3) * IC2_SLABF];
        for (int idx = t; idx < 3200; idx += 256) {
            int xx = idx >> 6, co = idx & 63;
            int xc = xx - 1;
            float v = 0.f;
            if ((unsigned)rr < 48u && (unsigned)xc < 48u)
                v = g_h[(((size_t)crop * 48 + rr) * 48 + xc) * 64 + co];
            dst[xx * 64 + co] = v;
        }
    };
    load_slab(r0 - 1); load_slab(r0); load_slab(r0 + 1);
    __syncthreads();

    float bias0 = bo[0];
    int px = t >> 2, q = t & 3;
    for (int r = r0; r < r0 + 24; r++) {
        if (t < 192) {
            const float* sm1 = &h4[((r - 1) & 3) * IC2_SLABF];
            const float* s0  = &h4[(r & 3) * IC2_SLABF];
            const float* sp1 = &h4[((r + 1) & 3) * IC2_SLABF];
            float s = 0.f;
#pragma unroll
            for (int tap = 0; tap < 9; tap++) {
                int dyi = tap / 3, dx = tap % 3;
                const float* slb = (dyi == 0) ? sm1 : (dyi == 1 ? s0 : sp1);
                const float* hr = &slb[(px + dx) * 64 + q * 16];
                const float* wr = &w2[tap * 64 + q * 16];
#pragma unroll
                for (int c = 0; c < 16; c++) s = fmaf(hr[c], wr[c], s);
            }
            s += __shfl_down_sync(0xffffffffu, s, 2, 4);
            s += __shfl_down_sync(0xffffffffu, s, 1, 4);
            if (q == 0)
                out[OFF_IOUT + ((size_t)crop * 48 + r) * 48 + px] =
                    1.f / (1.f + expf(-(s + bias0)));
        }
        if (r < r0 + 23) {
            load_slab(r + 2);             // writes (r+2)&3, not read this row
            __syncthreads();
        }
    }
}

// ================= launcher =============================================
extern "C" void kernel_launch(void* const* d_in, const int* in_sizes, int n_in,
                              void* d_out, int out_size)
{
    const float* df  = (const float*)d_in[0];
    const float* seg = (const float*)d_in[1];
    const float* Wc  = (const float*)d_in[2];
    const float* bc  = (const float*)d_in[3];
    const float* Wfc = (const float*)d_in[4];
    const float* bfc = (const float*)d_in[5];
    const float* Ws  = (const float*)d_in[6];
    const float* bs  = (const float*)d_in[7];
    const float* Wr  = (const float*)d_in[8];
    const float* br  = (const float*)d_in[9];
    const float* Wi  = (const float*)d_in[10];
    const float* bi  = (const float*)d_in[11];
    const float* Wo  = (const float*)d_in[12];
    const float* bo  = (const float*)d_in[13];
    float* out = (float*)d_out;
    (void)in_sizes; (void)n_in; (void)out_size;

    cudaFuncSetAttribute(icv1_kernel,
                         cudaFuncAttributeMaxDynamicSharedMemorySize, IC_SMEM);
    cudaFuncSetAttribute(icv2_kernel,
                         cudaFuncAttributeMaxDynamicSharedMemorySize, IC2_SMEM);

    zero_kernel<<<4, 1024>>>();

    dim3 gg(512, 8);                     // R7-proven layout
    gemm_kernel<0><<<gg, 256>>>(df, Wc, bc, Ws, Wr);
    gemm_kernel<1><<<gg, 256>>>(nullptr, Wfc, bfc, Ws, Wr);

    proj_reduce_kernel<<<256, 256>>>(bs, br);
    scan_kernel<<<1, 1024>>>(0);
    hist2_build_kernel<<<64, 1024>>>();
    scan_kernel<<<1, 1024>>>(1);
    compact_kernel<<<64, 1024>>>();
    sortgather_kernel<<<1, 1024>>>();

    nms_build_kernel<<<KTOP, 64>>>();
    nms_serial_kernel<<<1, 1024>>>(out);

    dim3 gic(500, 2);                    // half-crop blocks
    icv1_kernel<<<gic, 256, IC_SMEM>>>(seg, Wi, bi);
    icv2_kernel<<<gic, 256, IC2_SMEM>>>(Wo, bo, out);
}

// round 17
// speedup vs baseline: 1.0522x; 1.0522x over previous
#include <cuda_runtime.h>
#include <cstdint>

// ---------------- problem constants ----------------
#define HDIM 256
#define WDIM 256
#define FCH  1024
#define KTOP 2000
#define MAXOUT 500
#define CROPSZ 48
#define NPIX (HDIM*WDIM)           // 65536

// output layout (float32, concatenated in reference tuple order)
#define OFF_SCORES 0
#define OFF_DEC    500
#define OFF_IOUT   1500
#define OFF_ICRD   (1500 + 500*48*48)

// ---------------- device scratch ----------------
__device__ float g_y1[(size_t)NPIX * FCH];        // 268 MB
__device__ float g_part[(size_t)NPIX * 8 * 3];    // per-(row, bn) proj partials
__device__ float g_reg[NPIX * 2];
__device__ unsigned long long g_keys[NPIX];
__device__ int   g_hist1[4096];
__device__ int   g_hist2[4096];
__device__ int   g_cnt[4];        // [0]=compact count [1]=b* [2]=k2 [3]=s*
__device__ unsigned long long g_buf[4096];
__device__ float g_gy[KTOP], g_gx[KTOP], g_ts[KTOP];
__device__ unsigned g_close[KTOP * 64];
__device__ int   g_start[MAXOUT * 2];
__device__ __align__(16) float g_h[(size_t)MAXOUT * CROPSZ * CROPSZ * 64];

// ---------------- f32x2 helpers (sm_103a packed fp32, IEEE per lane) ------
__device__ __forceinline__ unsigned long long ffma2(unsigned long long a,
                                                    unsigned long long b,
                                                    unsigned long long c) {
    unsigned long long d;
    asm("fma.rn.f32x2 %0, %1, %2, %3;" : "=l"(d) : "l"(a), "l"(b), "l"(c));
    return d;
}
__device__ __forceinline__ unsigned long long pack2(float v) {
    unsigned long long d;
    asm("mov.b64 %0, {%1, %1};" : "=l"(d) : "f"(v));
    return d;
}

// ================= zero scratch (graph-replay safe) =====================
__global__ void zero_kernel()
{
    int i = blockIdx.x * blockDim.x + threadIdx.x;
    if (i < 4096) { g_hist1[i] = 0; g_hist2[i] = 0; g_buf[i] = 0ull; }
    if (i < 4) g_cnt[i] = 0;
}

// ================= GEMM: C = relu(A*B + bias), double-buffered ==========
// R7-proven config: KT=16, 34.8 KB static smem, grid(512,8) bm-fastest.
// Profiled: fma=74.2%, L1=74.0% co-saturated — structural ceiling.
// (R8 lesson: trading issue slots for crossbar bytes regresses.)
// MODE 0: implicit 3x3 conv (A=[256,256,128] HWC, B=Wc[1152,1024]) -> g_y1
// MODE 1: A=g_y1 [65536,1024], B=Wfc -> fused proj partials (no C store)
template<int MODE>
__global__ __launch_bounds__(256, 2)
void gemm_kernel(const float* __restrict__ Aext,
                 const float* __restrict__ B,
                 const float* __restrict__ bias,
                 const float* __restrict__ Ws,
                 const float* __restrict__ Wr)
{
    __shared__ __align__(16) float As[2][16 * 136];
    __shared__ __align__(16) float Bs[2][16 * 136];

    const int Ktot = MODE ? 1024 : 1152;
    const int NT = Ktot / 16;
    const float* A = MODE ? g_y1 : Aext;

    int tid = threadIdx.x;
    int tx = tid & 15, ty = tid >> 4;
    int bm = blockIdx.x, bn = blockIdx.y;
    int row0 = bm * 128;
    int co0  = bn * 128;
    int yrow = bm >> 1;                // conv mode
    int x0   = (bm & 1) * 128;

    int aci  = tid & 15;               // K index within tile
    int apx0 = tid >> 4;               // px start
    int bco  = tid & 127;
    int bk0  = tid >> 7;

    unsigned long long acc[8][4];
#pragma unroll
    for (int i = 0; i < 8; i++)
#pragma unroll
        for (int j = 0; j < 4; j++) acc[i][j] = 0ull;

    float Ar[8], Br[8];

    auto load_regs = [&](int k0) {
        if (MODE == 0) {
            int tap = k0 >> 7;
            int ci  = (k0 & 127) + aci;
            int dy  = tap / 3 - 1;
            int dxo = tap % 3 - 1;
            int syy = yrow + dy;
            bool rv = ((unsigned)syy < 256u);
#pragma unroll
            for (int i = 0; i < 8; i++) {
                int sxx = x0 + apx0 + i * 16 + dxo;
                float v = 0.f;
                if (rv && ((unsigned)sxx < 256u))
                    v = Aext[((size_t)(syy * 256 + sxx)) * 128 + ci];
                Ar[i] = v;
            }
        } else {
#pragma unroll
            for (int i = 0; i < 8; i++)
                Ar[i] = A[(size_t)(row0 + apx0 + i * 16) * 1024 + k0 + aci];
        }
#pragma unroll
        for (int i = 0; i < 8; i++)
            Br[i] = B[(size_t)(k0 + bk0 + i * 2) * 1024 + co0 + bco];
    };
    auto store_tile = [&](int buf) {
#pragma unroll
        for (int i = 0; i < 8; i++)
            As[buf][aci * 136 + apx0 + i * 16] = Ar[i];
#pragma unroll
        for (int i = 0; i < 8; i++)
            Bs[buf][(bk0 + i * 2) * 136 + bco] = Br[i];
    };

    load_regs(0);
    store_tile(0);
    __syncthreads();

    for (int kt = 0; kt < NT; kt++) {
        int cur = kt & 1;
        if (kt + 1 < NT) load_regs((kt + 1) * 16);

#pragma unroll
        for (int k = 0; k < 16; k++) {
            float4 a0 = *(const float4*)&As[cur][k * 136 + ty * 8];
            float4 a1 = *(const float4*)&As[cur][k * 136 + ty * 8 + 4];
            unsigned long long b0 = *(const unsigned long long*)&Bs[cur][k * 136 + tx * 2];
            unsigned long long b1 = *(const unsigned long long*)&Bs[cur][k * 136 + tx * 2 + 32];
            unsigned long long b2 = *(const unsigned long long*)&Bs[cur][k * 136 + tx * 2 + 64];
            unsigned long long b3 = *(const unsigned long long*)&Bs[cur][k * 136 + tx * 2 + 96];
            float av[8] = {a0.x, a0.y, a0.z, a0.w, a1.x, a1.y, a1.z, a1.w};
#pragma unroll
            for (int i = 0; i < 8; i++) {
                unsigned long long aa = pack2(av[i]);
                acc[i][0] = ffma2(aa, b0, acc[i][0]);
                acc[i][1] = ffma2(aa, b1, acc[i][1]);
                acc[i][2] = ffma2(aa, b2, acc[i][2]);
                acc[i][3] = ffma2(aa, b3, acc[i][3]);
            }
        }
        if (kt + 1 < NT) store_tile(cur ^ 1);
        __syncthreads();
    }

    if (MODE == 0) {
#pragma unroll
        for (int i = 0; i < 8; i++) {
            int row = row0 + ty * 8 + i;
#pragma unroll
            for (int j = 0; j < 4; j++) {
                float2 v = *reinterpret_cast<float2*>(&acc[i][j]);
                int co = co0 + tx * 2 + j * 32;
                float o0 = v.x + bias[co];
                float o1 = v.y + bias[co + 1];
                o0 = o0 > 0.f ? o0 : 0.f;
                o1 = o1 > 0.f ? o1 : 0.f;
                *(float2*)&g_y1[(size_t)row * 1024 + co] = make_float2(o0, o1);
            }
        }
    } else {
        float wsv[8], wr0[8], wr1[8], bv[8];
#pragma unroll
        for (int j = 0; j < 4; j++) {
            int co = co0 + tx * 2 + j * 32;
            wsv[2*j]   = Ws[co];      wsv[2*j+1] = Ws[co+1];
            wr0[2*j]   = Wr[2*co];    wr0[2*j+1] = Wr[2*co+2];
            wr1[2*j]   = Wr[2*co+1];  wr1[2*j+1] = Wr[2*co+3];
            bv[2*j]    = bias[co];    bv[2*j+1]  = bias[co+1];
        }
#pragma unroll
        for (int i = 0; i < 8; i++) {
            int row = row0 + ty * 8 + i;
            float s = 0.f, r0 = 0.f, r1 = 0.f;
#pragma unroll
            for (int j = 0; j < 4; j++) {
                float2 v = *reinterpret_cast<float2*>(&acc[i][j]);
                float o0 = v.x + bv[2*j];   o0 = o0 > 0.f ? o0 : 0.f;
                float o1 = v.y + bv[2*j+1]; o1 = o1 > 0.f ? o1 : 0.f;
                s  = fmaf(o0, wsv[2*j], s);   s  = fmaf(o1, wsv[2*j+1], s);
                r0 = fmaf(o0, wr0[2*j], r0);  r0 = fmaf(o1, wr0[2*j+1], r0);
                r1 = fmaf(o0, wr1[2*j], r1);  r1 = fmaf(o1, wr1[2*j+1], r1);
            }
#pragma unroll
            for (int off = 8; off; off >>= 1) {
                s  += __shfl_down_sync(0xffffffffu, s,  off, 16);
                r0 += __shfl_down_sync(0xffffffffu, r0, off, 16);
                r1 += __shfl_down_sync(0xffffffffu, r1, off, 16);
            }
            if (tx == 0) {
                size_t o = ((size_t)row * 8 + bn) * 3;
                g_part[o] = s; g_part[o+1] = r0; g_part[o+2] = r1;
            }
        }
    }
}

// ================= proj reduce: scores/reg/keys/hist ====================
__global__ void proj_reduce_kernel(const float* __restrict__ bs,
                                   const float* __restrict__ br)
{
    int row = blockIdx.x * blockDim.x + threadIdx.x;
    if (row >= NPIX) return;
    float s = 0.f, r0 = 0.f, r1 = 0.f;
    const float* p = &g_part[(size_t)row * 24];
#pragma unroll
    for (int bn = 0; bn < 8; bn++) {
        s  += p[bn*3];
        r0 += p[bn*3+1];
        r1 += p[bn*3+2];
    }
    float z = s + bs[0];
    float score = 1.f / (1.f + expf(-z));
    g_reg[2*row]   = r0 + br[0];
    g_reg[2*row+1] = r1 + br[1];
    unsigned sb = __float_as_uint(score);
    g_keys[row] = ((unsigned long long)sb << 32) | (unsigned)(~row);
    atomicAdd(&g_hist1[sb >> 20], 1);
}

// ================= histogram scan (suffix sums, find threshold) =========
// (histogram selected INSIDE the kernel — host-decayed __device__ pointers
//  silently read host shadow memory via ATS on GB300.)
__global__ void scan_kernel(int mode)
{
    __shared__ int sA[4096], sB[4096];
    const int* hist = (mode == 0) ? g_hist1 : g_hist2;
    int t = threadIdx.x;
    for (int i = t; i < 4096; i += 1024) sA[i] = hist[i];
    __syncthreads();
    int* src = sA; int* dst = sB;
    for (int d = 1; d < 4096; d <<= 1) {
        for (int i = t; i < 4096; i += 1024)
            dst[i] = src[i] + ((i + d < 4096) ? src[i + d] : 0);
        __syncthreads();
        int* tmp = src; src = dst; dst = tmp;
    }
    int kneed = (mode == 0) ? KTOP : g_cnt[2];
    for (int i = t; i < 4096; i += 1024) {
        if (src[i] >= kneed && (i == 4095 || src[i + 1] < kneed)) {
            if (mode == 0) {
                g_cnt[1] = i;
                g_cnt[2] = kneed - ((i < 4095) ? src[i + 1] : 0);
            } else {
                g_cnt[3] = i;
            }
        }
    }
}

__global__ void hist2_build_kernel()
{
    int i = blockIdx.x * blockDim.x + threadIdx.x;
    if (i >= NPIX) return;
    unsigned sb = (unsigned)(g_keys[i] >> 32);
    if ((int)(sb >> 20) == g_cnt[1])
        atomicAdd(&g_hist2[(sb >> 8) & 4095], 1);
}

__global__ void compact_kernel()
{
    int i = blockIdx.x * blockDim.x + threadIdx.x;
    if (i >= NPIX) return;
    unsigned long long key = g_keys[i];
    unsigned sb = (unsigned)(key >> 32);
    int bin = sb >> 20;
    int bstar = g_cnt[1], sstar = g_cnt[3];
    bool take = (bin > bstar) ||
                (bin == bstar && (int)((sb >> 8) & 4095) >= sstar);
    if (take) {
        int pos = atomicAdd(&g_cnt[0], 1);
        if (pos < 4096) g_buf[pos] = key;
    }
}

// sort 4096 keys (asc) in one block, gather top-2000 desc
__global__ void sortgather_kernel()
{
    __shared__ unsigned long long s[4096];
    int t = threadIdx.x;
    s[t] = g_buf[t]; s[t + 1024] = g_buf[t + 1024];
    s[t + 2048] = g_buf[t + 2048]; s[t + 3072] = g_buf[t + 3072];
    __syncthreads();
    for (int k = 2; k <= 4096; k <<= 1) {
        for (int j = k >> 1; j > 0; j >>= 1) {
#pragma unroll
            for (int p = 0; p < 2; p++) {
                int t2 = t + p * 1024;
                int i = ((t2 & ~(j - 1)) << 1) | (t2 & (j - 1));
                bool up = ((i & k) == 0);
                unsigned long long a = s[i], b = s[i + j];
                if ((a > b) == up) { s[i] = b; s[i + j] = a; }
            }
            __syncthreads();
        }
    }
    for (int r = t; r < KTOP; r += 1024) {
        unsigned long long e = s[4095 - r];
        unsigned idx = ~(unsigned)(e & 0xffffffffu);
        float sc = __uint_as_float((unsigned)(e >> 32));
        int yy = idx >> 8, xx = idx & 255;
        g_ts[r] = sc;
        g_gy[r] = (float)yy + 0.5f + g_reg[2 * idx];
        g_gx[r] = (float)xx + 0.5f + g_reg[2 * idx + 1];
    }
}

// ================= NMS ==================================================
__global__ void nms_build_kernel()
{
    int i = blockIdx.x;
    int w = threadIdx.x;
    float cy = g_gy[i], cx = g_gx[i];
    unsigned m = 0;
    if (w < 63) {
        int j0 = w * 32;
#pragma unroll 4
        for (int l = 0; l < 32; l++) {
            int j = j0 + l;
            if (j > i && j < KTOP) {
                float dy = g_gy[j] - cy, dx = g_gx[j] - cx;
                if (dy * dy + dx * dx < 1.0f) m |= 1u << l;
            }
        }
    }
    g_close[i * 64 + w] = m;
}

__global__ void nms_serial_kernel(float* __restrict__ out)
{
    __shared__ float sy[KTOP], sx[KTOP], ss[KTOP];
    __shared__ unsigned supw[64];
    __shared__ int sel[MAXOUT];
    int t = threadIdx.x;
    for (int i = t; i < KTOP; i += 1024) {
        sy[i] = g_gy[i]; sx[i] = g_gx[i]; ss[i] = g_ts[i];
    }
    if (t < 32) {   // warp 0: serial bitmask OR loop
        int lane = t;
        unsigned s0 = 0, s1 = 0;
        unsigned p0 = g_close[lane], p1 = g_close[lane + 32];
        for (int i = 0; i < KTOP; i++) {
            unsigned n0 = 0, n1 = 0;
            if (i + 1 < KTOP) {
                n0 = g_close[(i + 1) * 64 + lane];
                n1 = g_close[(i + 1) * 64 + lane + 32];
            }
            int wi = i >> 5;
            unsigned myv = (wi >= 32) ? s1 : s0;
            unsigned vv = __shfl_sync(0xffffffffu, myv, wi & 31);
            if (!((vv >> (i & 31)) & 1u)) { s0 |= p0; s1 |= p1; }
            p0 = n0; p1 = n1;
        }
        supw[lane] = s0; supw[lane + 32] = s1;
    }
    __syncthreads();
    if (t == 0) {
        int cnt = 0;
        for (int i = 0; i < KTOP && cnt < MAXOUT; i++)
            if (!((supw[i >> 5] >> (i & 31)) & 1u)) sel[cnt++] = i;
        for (int i = 0; i < KTOP && cnt < MAXOUT; i++)
            if ((supw[i >> 5] >> (i & 31)) & 1u) sel[cnt++] = i;
    }
    __syncthreads();
    if (t < MAXOUT) {
        int i = sel[t];
        bool sup = (supw[i >> 5] >> (i & 31)) & 1u;
        out[OFF_SCORES + t] = sup ? -1.0f : ss[i];
        out[OFF_DEC + 2 * t]     = sy[i] * 4.0f;
        out[OFF_DEC + 2 * t + 1] = sx[i] * 4.0f;
        float ly = sy[i] * 2.0f, lx = sx[i] * 2.0f;
        int sty = (int)fminf(fmaxf(rintf(ly - 24.0f), 0.f), 464.f);
        int stx = (int)fminf(fmaxf(rintf(lx - 24.0f), 0.f), 464.f);
        g_start[2 * t]     = sty;
        g_start[2 * t + 1] = stx;
    }
}

// ================= instance head ========================================
// conv1 (R13): half-crop blocks, grid (500,2) — wave-quantization fix.
#define IC_WFLOATS 18432                    // 9*32*64
#define IC_SLABROW (32 * 52)                // floats per slab row
#define IC_SLABFLOATS (10 * IC_SLABROW)     // 16640
#define IC_SMEM ((IC_WFLOATS + IC_SLABFLOATS) * 4)   // 140,288 B
__global__ __launch_bounds__(256, 1)
void icv1_kernel(const float* __restrict__ seg,
                 const float* __restrict__ Wi, const float* __restrict__ bi)
{
    extern __shared__ __align__(16) float dyn[];
    float* w_sh = dyn;                    // [tap*2048 + ci*64 + ch]
    float* slab = dyn + IC_WFLOATS;       // [(d*32 + ci)*52 + xx]

    int crop = blockIdx.x;
    int half = blockIdx.y;                // 0: rows 0..23, 1: rows 24..47
    int t = threadIdx.x;
    int lane = t & 31, wrp = t >> 5;      // 8 warps -> 8 rows per chunk
    int sy0 = g_start[2 * crop], sx0 = g_start[2 * crop + 1];

    for (int i = t; i < IC_WFLOATS; i += 256) w_sh[i] = Wi[i];
    float2 bp = *(const float2*)&bi[2 * lane];

    for (int c = 0; c < 3; c++) {
        int chunk = half * 3 + c;
        int gr0 = chunk * 8 - 1;
        __syncthreads();                  // prev chunk readers done
        for (int idx = t; idx < IC_SLABFLOATS; idx += 256) {
            int d = idx / IC_SLABROW;
            int rem = idx - d * IC_SLABROW;
            int xx = rem >> 5, ci = rem & 31;
            int gr = gr0 + d, xc = xx - 1;
            float v = 0.f;
            if ((unsigned)gr < 48u && (unsigned)xc < 48u)
                v = seg[((size_t)(sy0 + gr) * 512 + (sx0 + xc)) * 32 + ci];
            slab[(d * 32 + ci) * 52 + xx] = v;
        }
        __syncthreads();

        int r = chunk * 8 + wrp;
        unsigned long long acc2[48];
#pragma unroll
        for (int p = 0; p < 48; p++) acc2[p] = 0ull;

        for (int dy = 0; dy < 3; dy++) {
            const float* srow = &slab[(wrp + dy) * 32 * 52];
            const float* wbase = &w_sh[dy * 3 * 2048 + 2 * lane];
            for (int ci = 0; ci < 32; ci++) {
                const float* sr = srow + ci * 52;
                unsigned long long w0 = *(const unsigned long long*)&wbase[ci * 64];
                unsigned long long w1 = *(const unsigned long long*)&wbase[2048 + ci * 64];
                unsigned long long w2 = *(const unsigned long long*)&wbase[4096 + ci * 64];
#pragma unroll
                for (int j = 0; j < 13; j++) {
                    float4 a4 = *(const float4*)&sr[4 * j];
                    float av[4] = {a4.x, a4.y, a4.z, a4.w};
#pragma unroll
                    for (int l = 0; l < 4; l++) {
                        const int xx = 4 * j + l;
                        if (xx > 49) continue;
                        unsigned long long aa = pack2(av[l]);
                        if (xx <= 47)            acc2[xx]     = ffma2(aa, w0, acc2[xx]);
                        if (xx >= 1 && xx <= 48) acc2[xx - 1] = ffma2(aa, w1, acc2[xx - 1]);
                        if (xx >= 2)             acc2[xx - 2] = ffma2(aa, w2, acc2[xx - 2]);
                    }
                }
            }
        }

        float* dst = &g_h[(((size_t)crop * 48 + r) * 48) * 64 + 2 * lane];
#pragma unroll
        for (int px = 0; px < 48; px++) {
            float2 v = *reinterpret_cast<float2*>(&acc2[px]);
            float o0 = v.x + bp.x, o1 = v.y + bp.y;
            o0 = o0 > 0.f ? o0 : 0.f;
            o1 = o1 > 0.f ? o1 : 0.f;
            *(float2*)&dst[px * 64] = make_float2(o0, o1);
        }
    }
}

// conv2 (R14): half-crop rolling window, grid (500,2) — wave-quantization
// fix mirroring icv1. Each half owns output rows half*24 .. half*24+23 and
// its own 3-slab window; per-row arithmetic identical -> bit-identical.
// Also fuses instance_coords writes (each half writes its own rows).
__global__ __launch_bounds__(256)
void icv2_kernel(const float* __restrict__ Wo, const float* __restrict__ bo,
                 float* __restrict__ out)
{
    __shared__ float h_sh[3][50 * 64];    // padded-x slabs
    __shared__ float w2[576];
    __shared__ float red[192];
    int crop = blockIdx.x;
    int half = blockIdx.y;
    int r0 = half * 24;
    int t = threadIdx.x;
    int sy0 = g_start[2 * crop], sx0 = g_start[2 * crop + 1];
    for (int w = t; w < 576; w += 256) w2[w] = Wo[w];

    // coords for this half-crop (rows r0..r0+23)
    for (int idx = t; idx < 24 * CROPSZ; idx += 256) {
        int cy = r0 + idx / 48, cx = idx % 48;
        size_t o = OFF_ICRD + 2 * ((size_t)crop * 2304 + (size_t)cy * 48 + cx);
        out[o]     = (float)(sy0 + cy);
        out[o + 1] = (float)(sx0 + cx);
    }

    auto load_slab = [&](int rr, int b) {
        for (int idx = t; idx < 3200; idx += 256) {
            int xx = idx >> 6, co = idx & 63;
            int xc = xx - 1;
            float v = 0.f;
            if ((unsigned)rr < 48u && (unsigned)xc < 48u)
                v = g_h[(((size_t)crop * 48 + rr) * 48 + xc) * 64 + co];
            h_sh[b][xx * 64 + co] = v;
        }
    };
    // window slabs for first row r0: rows r0-1, r0, r0+1 placed at
    // buffer indices matching the rolling scheme below
    load_slab(r0,     r0 % 3);
    load_slab(r0 + 1, (r0 + 1) % 3);
    load_slab(r0 - 1, (r0 + 2) % 3);
    __syncthreads();

    float bias0 = bo[0];
    for (int r = r0; r < r0 + 24; r++) {
        if (t < 192) {
            int px = t >> 2, q = t & 3;
            const float* sm1 = h_sh[(r + 2) % 3];
            const float* s0  = h_sh[r % 3];
            const float* sp1 = h_sh[(r + 1) % 3];
            float s = 0.f;
#pragma unroll
            for (int tap = 0; tap < 9; tap++) {
                int dyi = tap / 3, dx = tap % 3;
                const float* slb = (dyi == 0) ? sm1 : (dyi == 1 ? s0 : sp1);
                const float* hr = &slb[(px + dx) * 64 + q * 16];
                const float* wr = &w2[tap * 64 + q * 16];
#pragma unroll
                for (int c = 0; c < 16; c++) s = fmaf(hr[c], wr[c], s);
            }
            red[t] = s;
        }
        __syncthreads();
        if (t < 48) {
            float s = red[4*t] + red[4*t+1] + red[4*t+2] + red[4*t+3] + bias0;
            out[OFF_IOUT + ((size_t)crop * 48 + r) * 48 + t] = 1.f / (1.f + expf(-s));
        }
        if (r < r0 + 23) load_slab(r + 2, (r + 2) % 3);
        __syncthreads();
    }
}

// ================= launcher =============================================
extern "C" void kernel_launch(void* const* d_in, const int* in_sizes, int n_in,
                              void* d_out, int out_size)
{
    const float* df  = (const float*)d_in[0];
    const float* seg = (const float*)d_in[1];
    const float* Wc  = (const float*)d_in[2];
    const float* bc  = (const float*)d_in[3];
    const float* Wfc = (const float*)d_in[4];
    const float* bfc = (const float*)d_in[5];
    const float* Ws  = (const float*)d_in[6];
    const float* bs  = (const float*)d_in[7];
    const float* Wr  = (const float*)d_in[8];
    const float* br  = (const float*)d_in[9];
    const float* Wi  = (const float*)d_in[10];
    const float* bi  = (const float*)d_in[11];
    const float* Wo  = (const float*)d_in[12];
    const float* bo  = (const float*)d_in[13];
    float* out = (float*)d_out;
    (void)in_sizes; (void)n_in; (void)out_size;

    cudaFuncSetAttribute(icv1_kernel,
                         cudaFuncAttributeMaxDynamicSharedMemorySize, IC_SMEM);

    zero_kernel<<<4, 1024>>>();

    dim3 gg(512, 8);                     // R7-proven layout
    gemm_kernel<0><<<gg, 256>>>(df, Wc, bc, Ws, Wr);
    gemm_kernel<1><<<gg, 256>>>(nullptr, Wfc, bfc, Ws, Wr);

    proj_reduce_kernel<<<256, 256>>>(bs, br);
    scan_kernel<<<1, 1024>>>(0);
    hist2_build_kernel<<<64, 1024>>>();
    scan_kernel<<<1, 1024>>>(1);
    compact_kernel<<<64, 1024>>>();
    sortgather_kernel<<<1, 1024>>>();

    nms_build_kernel<<<KTOP, 64>>>();
    nms_serial_kernel<<<1, 1024>>>(out);

    dim3 gic(500, 2);                    // half-crop blocks
    icv1_kernel<<<gic, 256, IC_SMEM>>>(seg, Wi, bi);
    icv2_kernel<<<gic, 256>>>(Wo, bo, out);
}